// round 6
// baseline (speedup 1.0000x reference)
#include <cuda_runtime.h>
#include <cuda_bf16.h>
#include <cstdint>

typedef unsigned long long u64;

#define BB 32
#define TT 256
#define II 128
#define HH 128
#define GG 512   // 4*H
#define CC 100
#define WS_PAD 132

// phase 2: per gate-row split of the 64 k-pairs
#define RREG 46                 // u64 pairs in registers per row (k = 0..91)
#define RSM  (64 - RREG)        // 18 pairs per row from smem     (k = 92..127)
#define RSM2 (RSM / 2)          // 9 ulonglong2 chunks per row

// ---------------- scratch (device globals; no allocation allowed) ----------
__device__ float g_gatesx[TT * BB * GG];      // [t][b][g]
__device__ float g_hist[(TT + 1) * BB * HH];  // [j][b][u], j=1..256 = h_1..h_256
__device__ float g_attn[BB * HH];
__device__ float g_q[BB * HH];                // q = h_T @ w1_top

__device__ __forceinline__ void fma2(u64 &acc, u64 a, u64 b) {
    asm("fma.rn.f32x2 %0, %1, %2, %0;" : "+l"(acc) : "l"(a), "l"(b));
}
__device__ __forceinline__ float sum2(u64 v) {
    float lo, hi;
    asm("mov.b64 {%0,%1}, %2;" : "=f"(lo), "=f"(hi) : "l"(v));
    return lo + hi;
}
// fast activations via MUFU ex2 (~1e-7 abs error, fine vs 1e-3 gate)
__device__ __forceinline__ float fast_sig(float x) {
    return __fdividef(1.0f, 1.0f + __expf(-x));
}
__device__ __forceinline__ float fast_tanh(float x) {
    return fmaf(-2.0f, __fdividef(1.0f, __expf(2.0f * x) + 1.0f), 1.0f);
}

// ---------------------------------------------------------------------------
// Phase 1: gates_x[t][b][g] = x[b,t,:] . w_ih[g,:] + b_ih[g] + b_hh[g]
// grid (T, 4) x 256 threads.
// ---------------------------------------------------------------------------
__global__ void __launch_bounds__(256, 2) phase1_kernel(
    const float* __restrict__ x, const float* __restrict__ w_ih,
    const float* __restrict__ b_ih, const float* __restrict__ b_hh)
{
    extern __shared__ float sm[];
    float* x_s = sm;                 // [32][128]
    float* ws  = sm + BB * II;       // [128][WS_PAD]
    const int t   = blockIdx.x;
    const int gq  = blockIdx.y;      // 0..3: which 128-gate tile
    const int tid = threadIdx.x;

    for (int i = tid; i < BB * II; i += 256) {
        int b = i >> 7, k = i & 127;
        x_s[i] = x[(b * TT + t) * II + k];
    }
    const float* wsrc = w_ih + gq * 128 * II;
    for (int i = tid; i < 128 * II; i += 256) {
        int gl = i >> 7, k = i & 127;
        ws[gl * WS_PAD + k] = wsrc[i];
    }
    if (t == 0 && gq == 0) {   // re-zero attention accumulator every launch
        for (int i = tid; i < BB * HH; i += 256) g_attn[i] = 0.0f;
    }
    __syncthreads();

    const int gl   = tid & 127;
    const int half = tid >> 7;
    const int g    = gq * 128 + gl;
    const float bias = b_ih[g] + b_hh[g];
    const float* wrow = ws + gl * WS_PAD;

    for (int bq = 0; bq < 2; bq++) {
        const int b0 = half * 16 + bq * 8;
        u64 acc[8];
        #pragma unroll
        for (int j = 0; j < 8; j++) acc[j] = 0ull;
        #pragma unroll
        for (int k0 = 0; k0 < II; k0 += 4) {
            ulonglong2 w = *(const ulonglong2*)(wrow + k0);
            #pragma unroll
            for (int j = 0; j < 8; j++) {
                ulonglong2 xv = *(const ulonglong2*)(x_s + (b0 + j) * II + k0);
                fma2(acc[j], w.x, xv.x);
                fma2(acc[j], w.y, xv.y);
            }
        }
        #pragma unroll
        for (int j = 0; j < 8; j++)
            g_gatesx[(t * BB + b0 + j) * GG + g] = sum2(acc[j]) + bias;
    }
}

// ---------------------------------------------------------------------------
// Phase 2: LSTM recurrence. 32 blocks (one per batch) x 256 threads.
// Unit u = tid>>1. Even thread (2u): rows u (i-gate), 256+u (g-gate).
// Odd thread (2u+1):               rows 128+u (f),   384+u (o).
// Gate exchange via shfl_xor(1); h double-buffered; ONE barrier per step.
// Weights k=0..91 register-resident per row; k=92..127 streamed from smem
// as [chunk][tid] ulonglong2 (conflict-free LDS.128).
// ---------------------------------------------------------------------------
__global__ void __launch_bounds__(256, 1) phase2_kernel(const float* __restrict__ w_hh)
{
    extern __shared__ float sm[];
    float* h_buf = sm;                         // [2][128]
    ulonglong2* wsA4 = (ulonglong2*)(sm + 256);          // [RSM2][256]
    ulonglong2* wsB4 = wsA4 + RSM2 * 256;                // [RSM2][256]
    const int b   = blockIdx.x;
    const int tid = threadIdx.x;
    const int u   = tid >> 1;
    const int odd = tid & 1;

    const int rowA = odd ? (128 + u) : u;          // f : i
    const int rowB = odd ? (384 + u) : (256 + u);  // o : g
    const float* wA = w_hh + rowA * HH;
    const float* wB = w_hh + rowB * HH;

    u64 wrA[RREG], wrB[RREG];
    #pragma unroll
    for (int i = 0; i < RREG; i++) {
        wrA[i] = *(const u64*)(wA + 2 * i);
        wrB[i] = *(const u64*)(wB + 2 * i);
    }
    #pragma unroll
    for (int j = 0; j < RSM2; j++) {
        wsA4[j * 256 + tid] = *(const ulonglong2*)(wA + 2 * RREG + 4 * j);
        wsB4[j * 256 + tid] = *(const ulonglong2*)(wB + 2 * RREG + 4 * j);
    }

    if (tid < 256) { h_buf[tid] = 0.0f; }   // zero both buffers (256 floats)
    float c = 0.0f;
    __syncthreads();

    const int stride_t = BB * GG;
    const float* gxpA = g_gatesx + b * GG + rowA;
    const float* gxpB = g_gatesx + b * GG + rowB;
    float gxnA = gxpA[0];
    float gxnB = gxpB[0];

    for (int t = 0; t < TT; t++) {
        const int p = t & 1;
        float gxA = gxnA, gxB = gxnB;
        if (t + 1 < TT) {
            gxnA = gxpA[(t + 1) * stride_t];
            gxnB = gxpB[(t + 1) * stride_t];
        }

        const ulonglong2* h4 = (const ulonglong2*)(h_buf + p * 128);  // 32 chunks

        u64 a0 = 0ull, a1 = 0ull, b0 = 0ull, b1 = 0ull;
        #pragma unroll
        for (int i = 0; i < RREG / 2; i++) {        // k = 0 .. 91
            ulonglong2 hv = h4[i];
            fma2(a0, wrA[2 * i],     hv.x);
            fma2(a1, wrA[2 * i + 1], hv.y);
            fma2(b0, wrB[2 * i],     hv.x);
            fma2(b1, wrB[2 * i + 1], hv.y);
        }
        #pragma unroll
        for (int j = 0; j < RSM2; j++) {            // k = 92 .. 127
            ulonglong2 hv = h4[RREG / 2 + j];
            ulonglong2 wa = wsA4[j * 256 + tid];
            ulonglong2 wb = wsB4[j * 256 + tid];
            fma2(a0, wa.x, hv.x);
            fma2(a1, wa.y, hv.y);
            fma2(b0, wb.x, hv.x);
            fma2(b1, wb.y, hv.y);
        }

        float gateA = gxA + sum2(a0) + sum2(a1);
        float gateB = gxB + sum2(b0) + sum2(b1);
        float aA = fast_sig(gateA);                        // i (even) / f (odd)
        float aB = odd ? fast_sig(gateB)                   // o
                       : fast_tanh(gateB);                 // g
        float xf = __shfl_xor_sync(0xffffffffu, aA, 1);
        float xo = __shfl_xor_sync(0xffffffffu, aB, 1);

        if (!odd) {
            c = xf * c + aA * aB;                   // sig(f)*c + sig(i)*tanh(g)
            float hv = xo * fast_tanh(c);           // sig(o)*tanh(c)
            h_buf[(1 - p) * 128 + u] = hv;
            g_hist[(t + 1) * (BB * HH) + b * HH + u] = hv;
        }
        __syncthreads();
    }
}

// ---------------------------------------------------------------------------
// Phase q: g_q[b][n] = sum_k h_T[k] * w1[k][n]   (w1 top half)
// grid 32 x 128 threads.
// ---------------------------------------------------------------------------
__global__ void __launch_bounds__(128, 8) phaseq_kernel(const float* __restrict__ w1)
{
    __shared__ float hf[HH];
    const int b = blockIdx.x, n = threadIdx.x;
    hf[n] = g_hist[TT * (BB * HH) + b * HH + n];
    __syncthreads();
    float q = 0.0f;
    #pragma unroll 4
    for (int k = 0; k < HH; k++) q += hf[k] * w1[k * HH + n];
    g_q[b * HH + n] = q;
}

// ---------------------------------------------------------------------------
// Phase 3a: final attention over memory h_1..h_255.
//   p_j[n] = sum_k h_j[k] * w1[H+k][n]
//   s_j    = sum_n w2[n] * tanh(q[b][n] + p_j[n])
//   attn[b][n] += sum_j s_j * h_j[n]
// grid (B, 8) x 256 threads; each block covers 32 j's in 4 tiles of 8.
// Only w1 bottom half loaded (q precomputed).
// ---------------------------------------------------------------------------
__global__ void __launch_bounds__(256, 1) phase3a_kernel(
    const float* __restrict__ w1, const float* __restrict__ w2)
{
    extern __shared__ float sm[];
    float* ws   = sm;                        // [128][WS_PAD]  (w1 bottom)
    float* w2_s = ws + 128 * WS_PAD;         // [128]
    float* hj_s = w2_s + 128;                // [8][128]
    float* red  = hj_s + 8 * 128;            // [8][4]
    float* s_t  = red + 32;                  // [8]
    const int b   = blockIdx.x;
    const int jc  = blockIdx.y;
    const int tid = threadIdx.x;
    const int n    = tid & 127;
    const int half = tid >> 7;
    const int lane = tid & 31;
    const int wl   = (tid >> 5) & 3;

    const float* w1b = w1 + HH * HH;         // bottom half
    for (int i = tid; i < HH * HH; i += 256) {
        int k = i >> 7, kk = i & 127;
        ws[k * WS_PAD + kk] = w1b[i];
    }
    if (tid < 128) w2_s[tid] = w2[tid];
    __syncthreads();

    const float q   = g_q[b * HH + n];
    const float w2n = w2_s[n];

    float accA = 0.0f;
    const int j0 = 1 + jc * 32;
    const int jb = half * 4;
    const float* wb = ws + n;

    for (int tile = 0; tile < 4; tile++) {
        int jt = j0 + tile * 8;
        for (int r = 0; r < 4; r++) {
            int lin = r * 256 + tid;
            int jj = lin >> 7, k = lin & 127;
            int j = jt + jj;
            hj_s[jj * 128 + k] = (j <= TT - 1) ? g_hist[j * (BB * HH) + b * HH + k] : 0.0f;
        }
        __syncthreads();

        float p0 = 0, p1 = 0, p2 = 0, p3 = 0;
        #pragma unroll 4
        for (int k = 0; k < HH; k++) {
            float w = wb[k * WS_PAD];
            p0 += hj_s[(jb + 0) * 128 + k] * w;
            p1 += hj_s[(jb + 1) * 128 + k] * w;
            p2 += hj_s[(jb + 2) * 128 + k] * w;
            p3 += hj_s[(jb + 3) * 128 + k] * w;
        }
        float sv[4];
        sv[0] = w2n * fast_tanh(q + p0);
        sv[1] = w2n * fast_tanh(q + p1);
        sv[2] = w2n * fast_tanh(q + p2);
        sv[3] = w2n * fast_tanh(q + p3);
        #pragma unroll
        for (int jj = 0; jj < 4; jj++) {
            float v = sv[jj];
            v += __shfl_down_sync(0xffffffffu, v, 16);
            v += __shfl_down_sync(0xffffffffu, v, 8);
            v += __shfl_down_sync(0xffffffffu, v, 4);
            v += __shfl_down_sync(0xffffffffu, v, 2);
            v += __shfl_down_sync(0xffffffffu, v, 1);
            if (lane == 0) red[(half * 4 + jj) * 4 + wl] = v;
        }
        __syncthreads();
        if (tid < 8)
            s_t[tid] = red[tid * 4 + 0] + red[tid * 4 + 1] + red[tid * 4 + 2] + red[tid * 4 + 3];
        __syncthreads();

        accA += s_t[jb + 0] * hj_s[(jb + 0) * 128 + n]
              + s_t[jb + 1] * hj_s[(jb + 1) * 128 + n]
              + s_t[jb + 2] * hj_s[(jb + 2) * 128 + n]
              + s_t[jb + 3] * hj_s[(jb + 3) * 128 + n];
        __syncthreads();   // protect hj_s / red / s_t before next tile
    }
    atomicAdd(&g_attn[b * HH + n], accA);
}

// ---------------------------------------------------------------------------
// Phase 3b: out[b] = (h_T + attn[b]) @ w_fc^T + b_fc      (32 x 100 output)
// ---------------------------------------------------------------------------
__global__ void __launch_bounds__(128, 8) phase3b_kernel(
    const float* __restrict__ w_fc, const float* __restrict__ b_fc,
    float* __restrict__ out)
{
    __shared__ float v_s[HH];
    const int b = blockIdx.x, tid = threadIdx.x;
    v_s[tid] = g_hist[TT * (BB * HH) + b * HH + tid] + g_attn[b * HH + tid];
    __syncthreads();
    if (tid < CC) {
        float acc = b_fc[tid];
        const float4* wr4 = (const float4*)(w_fc + tid * HH);
        const float4* v4  = (const float4*)v_s;
        #pragma unroll
        for (int k4 = 0; k4 < HH / 4; k4++) {
            float4 w = wr4[k4];
            float4 v = v4[k4];
            acc += w.x * v.x + w.y * v.y + w.z * v.z + w.w * v.w;
        }
        out[b * CC + tid] = acc;
    }
}

// ---------------------------------------------------------------------------
extern "C" void kernel_launch(void* const* d_in, const int* in_sizes, int n_in,
                              void* d_out, int out_size)
{
    const float* x    = (const float*)d_in[0];
    const float* w_ih = (const float*)d_in[1];
    const float* b_ih = (const float*)d_in[2];
    const float* w_hh = (const float*)d_in[3];
    const float* b_hh = (const float*)d_in[4];
    const float* w1   = (const float*)d_in[5];
    const float* w2   = (const float*)d_in[6];
    const float* w_fc = (const float*)d_in[7];
    const float* b_fc = (const float*)d_in[8];
    float* out = (float*)d_out;

    const int SM1 = (BB * II + 128 * WS_PAD) * (int)sizeof(float);                 // ~84 KB
    const int SM2 = 256 * (int)sizeof(float) + 2 * RSM2 * 256 * (int)sizeof(ulonglong2); // ~74.8 KB
    const int SM3 = (128 * WS_PAD + 128 + 8 * 128 + 32 + 8) * (int)sizeof(float);  // ~72.4 KB

    cudaFuncSetAttribute(phase1_kernel,  cudaFuncAttributeMaxDynamicSharedMemorySize, SM1);
    cudaFuncSetAttribute(phase2_kernel,  cudaFuncAttributeMaxDynamicSharedMemorySize, SM2);
    cudaFuncSetAttribute(phase3a_kernel, cudaFuncAttributeMaxDynamicSharedMemorySize, SM3);

    phase1_kernel <<<dim3(TT, 4), 256, SM1>>>(x, w_ih, b_ih, b_hh);
    phase2_kernel <<<BB, 256, SM2>>>(w_hh);
    phaseq_kernel <<<BB, HH>>>(w1);
    phase3a_kernel<<<dim3(BB, 8), 256, SM3>>>(w1, w2);
    phase3b_kernel<<<BB, HH>>>(w_fc, b_fc, out);
}